// round 14
// baseline (speedup 1.0000x reference)
#include <cuda_runtime.h>
#include <cuda_fp16.h>
#include <math.h>
#include <stdint.h>

// Problem constants
#define B_    4
#define CIN   16
#define T_    31
#define H_    128
#define W_    128
#define HID   16
#define HW    (H_*W_)

// Arch-specific feature gate: tcgen05 PTX only assembles for sm_103a/f targets.
#if (defined(__CUDA_ARCH_SPECIFIC__) && (__CUDA_ARCH_SPECIFIC__ >= 1000)) || \
    (defined(__CUDA_ARCH_FAMILY_SPECIFIC__) && (__CUDA_ARCH_FAMILY_SPECIFIC__ >= 1000))
#define TC_PATH 1
#else
#define TC_PATH 0
#endif

// ===========================================================================
// Persistent fused conv + fo-pool, software-pipelined over t.
// R14: ONE 512-thread CTA per SM handling 4 output h-rows (was 2 CTAs x 2
// rows): per-step sync/fence/mbar scaffolding amortized 2x, h-halo LDG
// redundancy 2.0->1.5x, no same-schedule 2-CTA barrier contention.
// 4 MMA tiles/step (M=128 px, N=32 co), double-buffered TMEM (256 cols).
// A: two dense ci-planes per slot, 16 B/pixel row; desc LBO=plane/16, SBO=8
// (HW-validated). B: SW128 blocked atoms (HW-validated).
// Epilogue: z = tanh.approx; f = 0.5*tanh.approx(gf/2)+0.5 (measured-safe).
// ===========================================================================
#define SLAB_H     6                          // 4 out rows + 2 halo
#define SLOT_ROWS  (SLAB_H*130)               // 780 pixel rows per slot
#define NROWS      (4*SLOT_ROWS)              // 3120 rows (4 slots)
#define PLANE_B    (NROWS*16)                 // 49920 B per ci-plane
#define SMEM_SLAB  0
#define SMEM_BMAT  100352                     // 98*1024 (>= 2*PLANE_B=99840)
#define BMAT_BYTES (28*1024)
#define SMEM_PTR   (SMEM_BMAT + BMAT_BYTES)   // 129024
#define SMEM_MBAR0 (SMEM_PTR + 8)
#define SMEM_MBAR1 (SMEM_PTR + 16)
#define SMEM_BIAS  (SMEM_PTR + 32)
#define SMEM_BYTES (SMEM_BIAS + 128)          // 129184

#define MMA_IDESC  0x8080010u                 // f16 in, f32 acc, M=128, N=32
#define SWZ128(x) ((x) ^ (((x) >> 3) & 0x70))

__device__ __forceinline__ uint32_t smem_u32(const void* p) {
    uint32_t a;
    asm("{ .reg .u64 t; cvta.to.shared.u64 t, %1; cvt.u32.u64 %0, t; }" : "=r"(a) : "l"(p));
    return a;
}

#if TC_PATH
__device__ __forceinline__ uint32_t elect_one() {
    uint32_t p;
    asm volatile("{\n\t.reg .pred p;\n\telect.sync _|p, 0xFFFFFFFF;\n\t"
                 "selp.b32 %0, 1, 0, p;\n\t}" : "=r"(p));
    return p;
}
__device__ __forceinline__ uint64_t make_desc(uint32_t addr, uint32_t lbo,
                                              uint32_t sbo, uint32_t layout) {
    uint64_t d = 0;
    d |= (uint64_t)(addr >> 4) & 0x3FFF;
    d |= ((uint64_t)lbo & 0x3FFF) << 16;
    d |= ((uint64_t)sbo & 0x3FFF) << 32;
    d |= (uint64_t)1 << 46;
    d |= ((uint64_t)layout & 0x7) << 61;
    return d;
}
__device__ __forceinline__ void mma_f16_ss(uint32_t d_tmem, uint64_t a_desc,
                                           uint64_t b_desc, uint32_t idesc,
                                           uint32_t enable) {
    asm volatile(
        "{\n\t.reg .pred p;\n\tsetp.ne.u32 p, %5, 0;\n\t"
        "tcgen05.mma.cta_group::1.kind::f16 [%0], %1, %2, %3, {%4,%4,%4,%4}, p;\n\t}"
        :: "r"(d_tmem), "l"(a_desc), "l"(b_desc), "r"(idesc), "r"(0u), "r"(enable)
        : "memory");
}
__device__ __forceinline__ void mbar_wait(uint32_t m, uint32_t parity) {
    uint32_t done;
    asm volatile("{\n\t.reg .pred p;\n\t"
        "mbarrier.try_wait.parity.acquire.cta.shared::cta.b64 p, [%1], %2;\n\t"
        "selp.b32 %0, 1, 0, p;\n\t}" : "=r"(done) : "r"(m), "r"(parity) : "memory");
    while (!done)
        asm volatile("{\n\t.reg .pred p;\n\t"
            "mbarrier.try_wait.parity.acquire.cta.shared::cta.b64 p, [%1], %2, 0x989680;\n\t"
            "selp.b32 %0, 1, 0, p;\n\t}" : "=r"(done) : "r"(m), "r"(parity) : "memory");
}

// Issue the 108 MMAs for one time step (4 tiles x 27 chunks), commit to mbar.
__device__ __forceinline__ void issue_step(int t, uint32_t tmem_d,
                                           uint64_t a_base, uint64_t b_base,
                                           uint32_t mbar) {
    #pragma unroll
    for (int hr = 0; hr < 4; hr++) {
        #pragma unroll
        for (int kc = 0; kc < 27; kc++) {
            const int kd = kc / 9, kh = (kc / 3) % 3, kw = kc % 3;
            const int rowoff = ((t + kd) & 3)*SLOT_ROWS + (hr + kh)*130 + kw;
            mma_f16_ss(tmem_d + hr*32,
                       a_base + (uint64_t)rowoff,
                       b_base + (uint64_t)((kc >> 2)*256 + (kc & 3)*2),
                       MMA_IDESC, kc > 0);
        }
    }
    asm volatile(
        "tcgen05.commit.cta_group::1.mbarrier::arrive::one.shared::cluster.b64 [%0];"
        :: "r"(mbar) : "memory");
}
__device__ __forceinline__ float tanh_approx(float x) {
    float r;
    asm("tanh.approx.f32 %0, %1;" : "=f"(r) : "f"(x));
    return r;
}
#endif

// Load slice s: thread owns pixel tid (hh 0..3); threads < 256 also own
// pixel 512+tid (hh 4..5). 16 coalesced LDG.32 per pixel, packed to half2.
__device__ __forceinline__ void load_px(const float* __restrict__ x,
                                        int bb, int gh, int w, int s,
                                        uint32_t v[8]) {
    const bool ok = ((unsigned)s < (unsigned)T_) && ((unsigned)gh < (unsigned)H_);
    const float* xb = x + (size_t)bb*CIN*T_*HW + (size_t)s*HW + (size_t)gh*W_ + w;
    float f[CIN];
    #pragma unroll
    for (int ci = 0; ci < CIN; ci++)
        f[ci] = ok ? xb[(size_t)ci*T_*HW] : 0.f;
    #pragma unroll
    for (int j = 0; j < 8; j++) {
        __half2 h2 = __floats2half2_rn(f[2*j], f[2*j + 1]);
        v[j] = *(uint32_t*)&h2;
    }
}
__device__ __forceinline__ void load_slice(const float* __restrict__ x,
                                           int bb, int hb, int s, int tid,
                                           uint32_t v[8], uint32_t v2[8]) {
    load_px(x, bb, hb + (tid >> 7) - 1, tid & 127, s, v);
    if (tid < 256)
        load_px(x, bb, hb + 4 + (tid >> 7) - 1, tid & 127, s, v2);
}

// Store slice into rolling slot: 2-4 STS.128, conflict-free.
__device__ __forceinline__ void store_px(char* smem, int row,
                                         const uint32_t v[8]) {
    #pragma unroll
    for (int pl = 0; pl < 2; pl++) {
        uint4 q = make_uint4(v[pl*4], v[pl*4 + 1], v[pl*4 + 2], v[pl*4 + 3]);
        *(uint4*)(smem + SMEM_SLAB + pl*PLANE_B + row*16) = q;
    }
}
__device__ __forceinline__ void store_slice(char* smem, int slot, int tid,
                                            const uint32_t v[8],
                                            const uint32_t v2[8]) {
    int base = slot*SLOT_ROWS + (tid & 127) + 1;
    store_px(smem, base + (tid >> 7)*130, v);
    if (tid < 256)
        store_px(smem, base + (4 + (tid >> 7))*130, v2);
}

__global__ __launch_bounds__(512, 1)
void qrnn_fused_kernel(const float* __restrict__ x,
                       const float* __restrict__ Wg,
                       const float* __restrict__ bias,
                       float* __restrict__ out)
{
#if TC_PATH
    extern __shared__ char smem[];
    const uint32_t smem_base = smem_u32(smem);
    float* s_bias = (float*)(smem + SMEM_BIAS);

    const int tid = threadIdx.x;
    const int wid = tid >> 5;
    const int hb  = blockIdx.x * 4;
    const int bb  = blockIdx.y;

    // ---- prologue ----
    if (wid == 0) {
        asm volatile("tcgen05.alloc.cta_group::1.sync.aligned.shared::cta.b32 [%0], %1;"
                     :: "r"(smem_base + SMEM_PTR), "r"(256u) : "memory");
        asm volatile("tcgen05.relinquish_alloc_permit.cta_group::1.sync.aligned;");
    }
    if (tid == 0) {
        asm volatile("mbarrier.init.shared.b64 [%0], %1;"
                     :: "r"(smem_base + SMEM_MBAR0), "r"(1u) : "memory");
        asm volatile("mbarrier.init.shared.b64 [%0], %1;"
                     :: "r"(smem_base + SMEM_MBAR1), "r"(1u) : "memory");
    }
    if (tid < 32) s_bias[tid] = bias[tid];

    // zero the A slab (covers halos, slice -1, and w-edge columns forever)
    for (int i = tid; i < (2*PLANE_B)/16; i += 512)
        *(uint4*)(smem + SMEM_SLAB + i*16) = make_uint4(0,0,0,0);

    // B: [co 32][k 432] K-major SW128 blocked atoms (HW-validated layout)
    for (int idx = tid; idx < 27*16*32; idx += 512) {
        int tap = idx % 27;
        int ci  = (idx / 27) & 15;
        int co  = idx / 432;
        int k   = tap*16 + ci;
        uint32_t byte_off = (uint32_t)(((co >> 3) + (k >> 6)*4)*1024
                                       + (co & 7)*128 + (k & 63)*2);
        *(__half*)(smem + SMEM_BMAT + SWZ128(byte_off)) = __float2half(Wg[idx]);
    }
    __syncthreads();   // slab zero visible before slice stores

    // preload slices 0 and 1 (slice -1 stays zero in slot 0)
    {
        uint32_t v0[8], v1[8];
        load_slice(x, bb, hb, 0, tid, v0, v1);
        store_slice(smem, 1, tid, v0, v1);
        load_slice(x, bb, hb, 1, tid, v0, v1);
        store_slice(smem, 2, tid, v0, v1);
    }
    asm volatile("fence.proxy.async.shared::cta;" ::: "memory");
    __syncthreads();

    uint32_t tmem_base;
    asm volatile("ld.shared.b32 %0, [%1];" : "=r"(tmem_base) : "r"(smem_base + SMEM_PTR));

    const uint64_t a_base = make_desc(smem_base + SMEM_SLAB, PLANE_B/16, 8, 0);
    const uint64_t b_base = make_desc(smem_base + SMEM_BMAT, 1, 64, 2);
    const bool issuer = (wid == 0) && elect_one();

    // issue step 0 into D0 (slots 0,1,2 ready), then prefetch slice 2
    if (issuer)
        issue_step(0, tmem_base, a_base, b_base, smem_base + SMEM_MBAR0);

    uint32_t v[8], v2[8];
    load_slice(x, bb, hb, 2, tid, v, v2);

    // epilogue mapping: warpgroup wg owns tile hr = wg, px = w
    const int wg = tid >> 7;
    const int px = tid & 127;
    const size_t out_rowbase = (size_t)(hb + wg)*W_ + px;

    float hstate[HID];
    #pragma unroll
    for (int c = 0; c < HID; c++) hstate[c] = 0.f;
    float bz[HID], bf[HID];
    #pragma unroll
    for (int c = 0; c < HID; c++) { bz[c] = s_bias[c]; bf[c] = s_bias[c + HID]; }

    // ---- pipelined main loop ----
    for (int t = 0; t < T_; t++) {
        // (1) store slice t+2 into slot (t+3)&3 (disjoint from in-flight MMA reads)
        store_slice(smem, (t + 3) & 3, tid, v, v2);
        asm volatile("fence.proxy.async.shared::cta;" ::: "memory");
        __syncthreads();

        // (2) issue NEXT step's MMAs into the other D buffer.
        if (t < T_ - 1 && issuer)
            issue_step(t + 1, tmem_base + ((t + 1) & 1)*128, a_base, b_base,
                       smem_base + (((t + 1) & 1) ? SMEM_MBAR1 : SMEM_MBAR0));

        // (3) prefetch slice t+3
        load_slice(x, bb, hb, t + 3, tid, v, v2);

        // (4) wait for MMA(t), read D[t&1], activation + recurrence + store
        mbar_wait(smem_base + ((t & 1) ? SMEM_MBAR1 : SMEM_MBAR0), (t >> 1) & 1);
        asm volatile("tcgen05.fence::after_thread_sync;" ::: "memory");

        uint32_t d[32];
        asm volatile(
            "tcgen05.ld.sync.aligned.32x32b.x32.b32 "
            "{%0,%1,%2,%3,%4,%5,%6,%7,%8,%9,%10,%11,%12,%13,%14,%15,"
            "%16,%17,%18,%19,%20,%21,%22,%23,%24,%25,%26,%27,%28,%29,%30,%31}, [%32];"
            : "=r"(d[0]),"=r"(d[1]),"=r"(d[2]),"=r"(d[3]),"=r"(d[4]),"=r"(d[5]),
              "=r"(d[6]),"=r"(d[7]),"=r"(d[8]),"=r"(d[9]),"=r"(d[10]),"=r"(d[11]),
              "=r"(d[12]),"=r"(d[13]),"=r"(d[14]),"=r"(d[15]),"=r"(d[16]),"=r"(d[17]),
              "=r"(d[18]),"=r"(d[19]),"=r"(d[20]),"=r"(d[21]),"=r"(d[22]),"=r"(d[23]),
              "=r"(d[24]),"=r"(d[25]),"=r"(d[26]),"=r"(d[27]),"=r"(d[28]),"=r"(d[29]),
              "=r"(d[30]),"=r"(d[31])
            : "r"(tmem_base + (t & 1)*128 + wg*32));
        asm volatile("tcgen05.wait::ld.sync.aligned;" ::: "memory");

        // Lean epilogue: z = tanh.approx(gz); f = 0.5*tanh.approx(gf/2)+0.5
        // (measured: tanh.approx moved rel_err by only ~5e-8 on this data).
        #pragma unroll
        for (int c = 0; c < HID; c++) {
            float gz = __uint_as_float(d[c])       + bz[c];
            float gf = __uint_as_float(d[c + HID]) + bf[c];
            float z  = tanh_approx(gz);
            float f  = fmaf(tanh_approx(0.5f * gf), 0.5f, 0.5f);
            hstate[c] = f * (hstate[c] - z) + z;
            out[((size_t)(bb*HID + c)*T_ + t)*HW + out_rowbase] = hstate[c];
        }

        // (5) order this step's TMEM reads before MMA(t+2) rewrites D[t&1].
        asm volatile("tcgen05.fence::before_thread_sync;" ::: "memory");
    }

    __syncthreads();
    if (wid == 0)
        asm volatile("tcgen05.dealloc.cta_group::1.sync.aligned.b32 %0, %1;"
                     :: "r"(tmem_base), "r"(256u));
#endif  // TC_PATH
}

extern "C" void kernel_launch(void* const* d_in, const int* in_sizes, int n_in,
                              void* d_out, int out_size)
{
    (void)in_sizes; (void)n_in; (void)out_size;
    const float* x    = (const float*)d_in[0];
    const float* Wg   = (const float*)d_in[1];
    const float* bias = (const float*)d_in[2];
    float* out = (float*)d_out;

    cudaFuncSetAttribute(qrnn_fused_kernel,
                         cudaFuncAttributeMaxDynamicSharedMemorySize, SMEM_BYTES);

    dim3 grid(H_ / 4, B_);   // 32 x 4 = 128 CTAs, 1/SM (512 thr, 129KB smem)
    qrnn_fused_kernel<<<grid, 512, SMEM_BYTES>>>(x, Wg, bias, out);
}

// round 15
// speedup vs baseline: 1.2127x; 1.2127x over previous
#include <cuda_runtime.h>
#include <cuda_fp16.h>
#include <math.h>
#include <stdint.h>

// Problem constants
#define B_    4
#define CIN   16
#define T_    31
#define H_    128
#define W_    128
#define HID   16
#define HW    (H_*W_)

// Arch-specific feature gate: tcgen05 PTX only assembles for sm_103a/f targets.
#if (defined(__CUDA_ARCH_SPECIFIC__) && (__CUDA_ARCH_SPECIFIC__ >= 1000)) || \
    (defined(__CUDA_ARCH_FAMILY_SPECIFIC__) && (__CUDA_ARCH_FAMILY_SPECIFIC__ >= 1000))
#define TC_PATH 1
#else
#define TC_PATH 0
#endif

// ===========================================================================
// Persistent fused conv + fo-pool, software-pipelined over t.
// R15 = R13 skeleton (2 CTAs/SM x 2 h-rows x 256 thr — best config, 119.2us;
// the 1-CTA/SM R14 variant regressed because the second resident CTA is the
// latency-hider) + R14's 2-MUFU epilogue (f = 0.5*tanh(gf/2)+0.5, measured
// rel_err delta +5e-7). MUFU cost/SMSP/step: 1536 -> 1024 cyc.
// A: two dense ci-planes, LBO=plane/16, SBO=8 (HW-validated).
// B: SW128 blocked atoms (HW-validated). Conflict-free STS.128 fill.
// ===========================================================================
#define NROWS      2080                       // 4 slots * 520 rows
#define PLANE_B    (NROWS*16)                 // 33280 B per ci-plane
#define SMEM_SLAB  0
#define SMEM_BMAT  (2*PLANE_B)                // 66560, 1024-aligned
#define BMAT_BYTES (28*1024)
#define SMEM_PTR   (SMEM_BMAT + BMAT_BYTES)   // 95232
#define SMEM_MBAR0 (SMEM_PTR + 8)
#define SMEM_MBAR1 (SMEM_PTR + 16)
#define SMEM_BIAS  (SMEM_PTR + 32)
#define SMEM_BYTES (SMEM_BIAS + 128)

#define MMA_IDESC  0x8080010u                 // f16 in, f32 acc, M=128, N=32
#define SWZ128(x) ((x) ^ (((x) >> 3) & 0x70))

__device__ __forceinline__ uint32_t smem_u32(const void* p) {
    uint32_t a;
    asm("{ .reg .u64 t; cvta.to.shared.u64 t, %1; cvt.u32.u64 %0, t; }" : "=r"(a) : "l"(p));
    return a;
}

#if TC_PATH
__device__ __forceinline__ uint32_t elect_one() {
    uint32_t p;
    asm volatile("{\n\t.reg .pred p;\n\telect.sync _|p, 0xFFFFFFFF;\n\t"
                 "selp.b32 %0, 1, 0, p;\n\t}" : "=r"(p));
    return p;
}
__device__ __forceinline__ uint64_t make_desc(uint32_t addr, uint32_t lbo,
                                              uint32_t sbo, uint32_t layout) {
    uint64_t d = 0;
    d |= (uint64_t)(addr >> 4) & 0x3FFF;
    d |= ((uint64_t)lbo & 0x3FFF) << 16;
    d |= ((uint64_t)sbo & 0x3FFF) << 32;
    d |= (uint64_t)1 << 46;
    d |= ((uint64_t)layout & 0x7) << 61;
    return d;
}
__device__ __forceinline__ void mma_f16_ss(uint32_t d_tmem, uint64_t a_desc,
                                           uint64_t b_desc, uint32_t idesc,
                                           uint32_t enable) {
    asm volatile(
        "{\n\t.reg .pred p;\n\tsetp.ne.u32 p, %5, 0;\n\t"
        "tcgen05.mma.cta_group::1.kind::f16 [%0], %1, %2, %3, {%4,%4,%4,%4}, p;\n\t}"
        :: "r"(d_tmem), "l"(a_desc), "l"(b_desc), "r"(idesc), "r"(0u), "r"(enable)
        : "memory");
}
__device__ __forceinline__ void mbar_wait(uint32_t m, uint32_t parity) {
    uint32_t done;
    asm volatile("{\n\t.reg .pred p;\n\t"
        "mbarrier.try_wait.parity.acquire.cta.shared::cta.b64 p, [%1], %2;\n\t"
        "selp.b32 %0, 1, 0, p;\n\t}" : "=r"(done) : "r"(m), "r"(parity) : "memory");
    while (!done)
        asm volatile("{\n\t.reg .pred p;\n\t"
            "mbarrier.try_wait.parity.acquire.cta.shared::cta.b64 p, [%1], %2, 0x989680;\n\t"
            "selp.b32 %0, 1, 0, p;\n\t}" : "=r"(done) : "r"(m), "r"(parity) : "memory");
}

// Issue the 54 MMAs for one time step into D buffer (tmem_d), commit to mbar.
__device__ __forceinline__ void issue_step(int t, uint32_t tmem_d,
                                           uint64_t a_base, uint64_t b_base,
                                           uint32_t mbar) {
    #pragma unroll
    for (int hr = 0; hr < 2; hr++) {
        #pragma unroll
        for (int kc = 0; kc < 27; kc++) {
            const int kd = kc / 9, kh = (kc / 3) % 3, kw = kc % 3;
            const int rowoff = ((t + kd) & 3)*520 + (hr + kh)*130 + kw;
            mma_f16_ss(tmem_d + hr*32,
                       a_base + (uint64_t)rowoff,
                       b_base + (uint64_t)((kc >> 2)*256 + (kc & 3)*2),
                       MMA_IDESC, kc > 0);
        }
    }
    asm volatile(
        "tcgen05.commit.cta_group::1.mbarrier::arrive::one.shared::cluster.b64 [%0];"
        :: "r"(mbar) : "memory");
}
__device__ __forceinline__ float tanh_approx(float x) {
    float r;
    asm("tanh.approx.f32 %0, %1;" : "=f"(r) : "f"(x));
    return r;
}
#endif

// Load one t-slice: thread owns pixels tid and tid+256 of the 512-pixel tile
// (pixel = hh*128 + w). 16 coalesced LDG.32 per pixel, packed to 8 half2.
__device__ __forceinline__ void load_slice(const float* __restrict__ x,
                                           int bb, int hb, int s, int tid,
                                           uint32_t v[16]) {
    #pragma unroll
    for (int pp = 0; pp < 2; pp++) {
        int p  = tid + pp*256;
        int hh = p >> 7;
        int w  = p & 127;
        int gh = hb + hh - 1;
        const bool ok = ((unsigned)s < (unsigned)T_) && ((unsigned)gh < (unsigned)H_);
        const float* xb = x + (size_t)bb*CIN*T_*HW + (size_t)s*HW + (size_t)gh*W_ + w;
        float f[CIN];
        #pragma unroll
        for (int ci = 0; ci < CIN; ci++)
            f[ci] = ok ? xb[(size_t)ci*T_*HW] : 0.f;
        #pragma unroll
        for (int j = 0; j < 8; j++) {
            __half2 h2 = __floats2half2_rn(f[2*j], f[2*j + 1]);
            v[pp*8 + j] = *(uint32_t*)&h2;
        }
    }
}

// Store slice into rolling slot: 4 STS.128, conflict-free.
__device__ __forceinline__ void store_slice(char* smem, int slot, int tid,
                                            const uint32_t v[16]) {
    #pragma unroll
    for (int pp = 0; pp < 2; pp++) {
        int p  = tid + pp*256;
        int hh = p >> 7;
        int w  = p & 127;
        int row = slot*520 + hh*130 + (w + 1);
        #pragma unroll
        for (int pl = 0; pl < 2; pl++) {
            uint4 q = make_uint4(v[pp*8 + pl*4], v[pp*8 + pl*4 + 1],
                                 v[pp*8 + pl*4 + 2], v[pp*8 + pl*4 + 3]);
            *(uint4*)(smem + SMEM_SLAB + pl*PLANE_B + row*16) = q;
        }
    }
}

__global__ __launch_bounds__(256, 2)
void qrnn_fused_kernel(const float* __restrict__ x,
                       const float* __restrict__ Wg,
                       const float* __restrict__ bias,
                       float* __restrict__ out)
{
#if TC_PATH
    extern __shared__ char smem[];
    const uint32_t smem_base = smem_u32(smem);
    float* s_bias = (float*)(smem + SMEM_BIAS);

    const int tid = threadIdx.x;
    const int wid = tid >> 5;
    const int hb  = blockIdx.x * 2;
    const int bb  = blockIdx.y;

    // ---- prologue ----
    if (wid == 0) {
        asm volatile("tcgen05.alloc.cta_group::1.sync.aligned.shared::cta.b32 [%0], %1;"
                     :: "r"(smem_base + SMEM_PTR), "r"(128u) : "memory");
        asm volatile("tcgen05.relinquish_alloc_permit.cta_group::1.sync.aligned;");
    }
    if (tid == 0) {
        asm volatile("mbarrier.init.shared.b64 [%0], %1;"
                     :: "r"(smem_base + SMEM_MBAR0), "r"(1u) : "memory");
        asm volatile("mbarrier.init.shared.b64 [%0], %1;"
                     :: "r"(smem_base + SMEM_MBAR1), "r"(1u) : "memory");
    }
    if (tid < 32) s_bias[tid] = bias[tid];

    // zero the A slab (covers halos, slice -1, and w-edge columns forever)
    for (int i = tid; i < (2*PLANE_B)/16; i += 256)
        *(uint4*)(smem + SMEM_SLAB + i*16) = make_uint4(0,0,0,0);

    // B: [co 32][k 432] K-major SW128 blocked atoms (HW-validated layout)
    for (int idx = tid; idx < 27*16*32; idx += 256) {
        int tap = idx % 27;
        int ci  = (idx / 27) & 15;
        int co  = idx / 432;
        int k   = tap*16 + ci;
        uint32_t byte_off = (uint32_t)(((co >> 3) + (k >> 6)*4)*1024
                                       + (co & 7)*128 + (k & 63)*2);
        *(__half*)(smem + SMEM_BMAT + SWZ128(byte_off)) = __float2half(Wg[idx]);
    }
    __syncthreads();   // slab zero visible before slice stores

    // preload slices 0 and 1 (slice -1 stays zero in slot 0)
    {
        uint32_t v0[16];
        load_slice(x, bb, hb, 0, tid, v0);
        store_slice(smem, 1, tid, v0);
        load_slice(x, bb, hb, 1, tid, v0);
        store_slice(smem, 2, tid, v0);
    }
    asm volatile("fence.proxy.async.shared::cta;" ::: "memory");
    __syncthreads();

    uint32_t tmem_base;
    asm volatile("ld.shared.b32 %0, [%1];" : "=r"(tmem_base) : "r"(smem_base + SMEM_PTR));

    const uint64_t a_base = make_desc(smem_base + SMEM_SLAB, PLANE_B/16, 8, 0);
    const uint64_t b_base = make_desc(smem_base + SMEM_BMAT, 1, 64, 2);
    const bool issuer = (wid == 0) && elect_one();

    // issue step 0 into D0 (slots 0,1,2 ready), then prefetch slice 2
    if (issuer)
        issue_step(0, tmem_base, a_base, b_base, smem_base + SMEM_MBAR0);

    uint32_t v[16];
    load_slice(x, bb, hb, 2, tid, v);

    // epilogue mapping: warpgroup wg owns tile hr = wg, px = w
    const int wg = tid >> 7;
    const int px = tid & 127;
    const size_t out_rowbase = (size_t)(hb + wg)*W_ + px;

    float hstate[HID];
    #pragma unroll
    for (int c = 0; c < HID; c++) hstate[c] = 0.f;
    float bz[HID], bf[HID];
    #pragma unroll
    for (int c = 0; c < HID; c++) { bz[c] = s_bias[c]; bf[c] = s_bias[c + HID]; }

    // ---- pipelined main loop ----
    for (int t = 0; t < T_; t++) {
        // (1) store slice t+2 into slot (t+3)&3 (disjoint from in-flight MMA reads)
        store_slice(smem, (t + 3) & 3, tid, v);
        asm volatile("fence.proxy.async.shared::cta;" ::: "memory");
        __syncthreads();

        // (2) issue NEXT step's MMAs into the other D buffer.
        if (t < T_ - 1 && issuer)
            issue_step(t + 1, tmem_base + ((t + 1) & 1)*64, a_base, b_base,
                       smem_base + (((t + 1) & 1) ? SMEM_MBAR1 : SMEM_MBAR0));

        // (3) prefetch slice t+3
        load_slice(x, bb, hb, t + 3, tid, v);

        // (4) wait for MMA(t), read D[t&1], activation + recurrence + store
        mbar_wait(smem_base + ((t & 1) ? SMEM_MBAR1 : SMEM_MBAR0), (t >> 1) & 1);
        asm volatile("tcgen05.fence::after_thread_sync;" ::: "memory");

        uint32_t d[32];
        asm volatile(
            "tcgen05.ld.sync.aligned.32x32b.x32.b32 "
            "{%0,%1,%2,%3,%4,%5,%6,%7,%8,%9,%10,%11,%12,%13,%14,%15,"
            "%16,%17,%18,%19,%20,%21,%22,%23,%24,%25,%26,%27,%28,%29,%30,%31}, [%32];"
            : "=r"(d[0]),"=r"(d[1]),"=r"(d[2]),"=r"(d[3]),"=r"(d[4]),"=r"(d[5]),
              "=r"(d[6]),"=r"(d[7]),"=r"(d[8]),"=r"(d[9]),"=r"(d[10]),"=r"(d[11]),
              "=r"(d[12]),"=r"(d[13]),"=r"(d[14]),"=r"(d[15]),"=r"(d[16]),"=r"(d[17]),
              "=r"(d[18]),"=r"(d[19]),"=r"(d[20]),"=r"(d[21]),"=r"(d[22]),"=r"(d[23]),
              "=r"(d[24]),"=r"(d[25]),"=r"(d[26]),"=r"(d[27]),"=r"(d[28]),"=r"(d[29]),
              "=r"(d[30]),"=r"(d[31])
            : "r"(tmem_base + (t & 1)*64 + wg*32));
        asm volatile("tcgen05.wait::ld.sync.aligned;" ::: "memory");

        // 2-MUFU epilogue (R14-validated math, +5e-7 rel_err):
        //   z = tanh.approx(gz);  f = 0.5*tanh.approx(gf/2) + 0.5
        #pragma unroll
        for (int c = 0; c < HID; c++) {
            float gz = __uint_as_float(d[c])       + bz[c];
            float gf = __uint_as_float(d[c + HID]) + bf[c];
            float z  = tanh_approx(gz);
            float f  = fmaf(tanh_approx(0.5f * gf), 0.5f, 0.5f);
            hstate[c] = f * (hstate[c] - z) + z;
            out[((size_t)(bb*HID + c)*T_ + t)*HW + out_rowbase] = hstate[c];
        }

        // (5) order this step's TMEM reads before MMA(t+2) rewrites D[t&1].
        asm volatile("tcgen05.fence::before_thread_sync;" ::: "memory");
    }

    __syncthreads();
    if (wid == 0)
        asm volatile("tcgen05.dealloc.cta_group::1.sync.aligned.b32 %0, %1;"
                     :: "r"(tmem_base), "r"(128u));
#endif  // TC_PATH
}

extern "C" void kernel_launch(void* const* d_in, const int* in_sizes, int n_in,
                              void* d_out, int out_size)
{
    (void)in_sizes; (void)n_in; (void)out_size;
    const float* x    = (const float*)d_in[0];
    const float* Wg   = (const float*)d_in[1];
    const float* bias = (const float*)d_in[2];
    float* out = (float*)d_out;

    cudaFuncSetAttribute(qrnn_fused_kernel,
                         cudaFuncAttributeMaxDynamicSharedMemorySize, SMEM_BYTES);

    dim3 grid(H_ / 2, B_);   // 64 x 4 = 256 CTAs, 2/SM resident -> 1 wave
    qrnn_fused_kernel<<<grid, 256, SMEM_BYTES>>>(x, Wg, bias, out);
}

// round 16
// speedup vs baseline: 1.2644x; 1.0426x over previous
#include <cuda_runtime.h>
#include <cuda_fp16.h>
#include <math.h>
#include <stdint.h>

// Problem constants
#define B_    4
#define CIN   16
#define T_    31
#define H_    128
#define W_    128
#define HID   16
#define HW    (H_*W_)

// Arch-specific feature gate: tcgen05 PTX only assembles for sm_103a/f targets.
#if (defined(__CUDA_ARCH_SPECIFIC__) && (__CUDA_ARCH_SPECIFIC__ >= 1000)) || \
    (defined(__CUDA_ARCH_FAMILY_SPECIFIC__) && (__CUDA_ARCH_FAMILY_SPECIFIC__ >= 1000))
#define TC_PATH 1
#else
#define TC_PATH 0
#endif

// ===========================================================================
// Persistent fused conv + fo-pool.
// R16: TWO timesteps per iteration (16 iters, was 31): one __syncthreads +
// one fence-pair per 2 steps. MMAs for steps t,t+1 issued up front into
// TMEM tiles 0-3 with two commits (mbar0=step t, mbar1=step t+1) so
// MMA(t+1) still overlaps epilogue(t). Slice stores move post-wait:
//   after mbar0: slot t&3 (slice t-1) dead -> store slice t+3
//   after mbar1: slot (t+1)&3 (slice t) dead -> store slice t+4
// Base config = R15 champion: 2 CTAs/SM x 2 h-rows x 256 thr, 4-slot slab,
// A: two dense ci-planes LBO=plane/16 SBO=8 (HW-validated), B: SW128
// blocked atoms (HW-validated), conflict-free STS.128 fill, 2-MUFU epilogue.
// ===========================================================================
#define NROWS      2080                       // 4 slots * 520 rows
#define PLANE_B    (NROWS*16)                 // 33280 B per ci-plane
#define SMEM_SLAB  0
#define SMEM_BMAT  (2*PLANE_B)                // 66560, 1024-aligned
#define BMAT_BYTES (28*1024)
#define SMEM_PTR   (SMEM_BMAT + BMAT_BYTES)   // 95232
#define SMEM_MBAR0 (SMEM_PTR + 8)
#define SMEM_MBAR1 (SMEM_PTR + 16)
#define SMEM_BIAS  (SMEM_PTR + 32)
#define SMEM_BYTES (SMEM_BIAS + 128)

#define MMA_IDESC  0x8080010u                 // f16 in, f32 acc, M=128, N=32
#define SWZ128(x) ((x) ^ (((x) >> 3) & 0x70))

__device__ __forceinline__ uint32_t smem_u32(const void* p) {
    uint32_t a;
    asm("{ .reg .u64 t; cvta.to.shared.u64 t, %1; cvt.u32.u64 %0, t; }" : "=r"(a) : "l"(p));
    return a;
}

#if TC_PATH
__device__ __forceinline__ uint32_t elect_one() {
    uint32_t p;
    asm volatile("{\n\t.reg .pred p;\n\telect.sync _|p, 0xFFFFFFFF;\n\t"
                 "selp.b32 %0, 1, 0, p;\n\t}" : "=r"(p));
    return p;
}
__device__ __forceinline__ uint64_t make_desc(uint32_t addr, uint32_t lbo,
                                              uint32_t sbo, uint32_t layout) {
    uint64_t d = 0;
    d |= (uint64_t)(addr >> 4) & 0x3FFF;
    d |= ((uint64_t)lbo & 0x3FFF) << 16;
    d |= ((uint64_t)sbo & 0x3FFF) << 32;
    d |= (uint64_t)1 << 46;
    d |= ((uint64_t)layout & 0x7) << 61;
    return d;
}
__device__ __forceinline__ void mma_f16_ss(uint32_t d_tmem, uint64_t a_desc,
                                           uint64_t b_desc, uint32_t idesc,
                                           uint32_t enable) {
    asm volatile(
        "{\n\t.reg .pred p;\n\tsetp.ne.u32 p, %5, 0;\n\t"
        "tcgen05.mma.cta_group::1.kind::f16 [%0], %1, %2, %3, {%4,%4,%4,%4}, p;\n\t}"
        :: "r"(d_tmem), "l"(a_desc), "l"(b_desc), "r"(idesc), "r"(0u), "r"(enable)
        : "memory");
}
__device__ __forceinline__ void mbar_wait(uint32_t m, uint32_t parity) {
    uint32_t done;
    asm volatile("{\n\t.reg .pred p;\n\t"
        "mbarrier.try_wait.parity.acquire.cta.shared::cta.b64 p, [%1], %2;\n\t"
        "selp.b32 %0, 1, 0, p;\n\t}" : "=r"(done) : "r"(m), "r"(parity) : "memory");
    while (!done)
        asm volatile("{\n\t.reg .pred p;\n\t"
            "mbarrier.try_wait.parity.acquire.cta.shared::cta.b64 p, [%1], %2, 0x989680;\n\t"
            "selp.b32 %0, 1, 0, p;\n\t}" : "=r"(done) : "r"(m), "r"(parity) : "memory");
}

// Issue the 54 MMAs for one time step into D buffer (tmem_d), commit to mbar.
__device__ __forceinline__ void issue_step(int t, uint32_t tmem_d,
                                           uint64_t a_base, uint64_t b_base,
                                           uint32_t mbar) {
    #pragma unroll
    for (int hr = 0; hr < 2; hr++) {
        #pragma unroll
        for (int kc = 0; kc < 27; kc++) {
            const int kd = kc / 9, kh = (kc / 3) % 3, kw = kc % 3;
            const int rowoff = ((t + kd) & 3)*520 + (hr + kh)*130 + kw;
            mma_f16_ss(tmem_d + hr*32,
                       a_base + (uint64_t)rowoff,
                       b_base + (uint64_t)((kc >> 2)*256 + (kc & 3)*2),
                       MMA_IDESC, kc > 0);
        }
    }
    asm volatile(
        "tcgen05.commit.cta_group::1.mbarrier::arrive::one.shared::cluster.b64 [%0];"
        :: "r"(mbar) : "memory");
}
__device__ __forceinline__ float tanh_approx(float x) {
    float r;
    asm("tanh.approx.f32 %0, %1;" : "=f"(r) : "f"(x));
    return r;
}
#endif

// Load one t-slice: thread owns pixels tid and tid+256 of the 512-pixel tile
// (pixel = hh*128 + w). 16 coalesced LDG.32 per pixel, packed to 8 half2.
__device__ __forceinline__ void load_slice(const float* __restrict__ x,
                                           int bb, int hb, int s, int tid,
                                           uint32_t v[16]) {
    #pragma unroll
    for (int pp = 0; pp < 2; pp++) {
        int p  = tid + pp*256;
        int hh = p >> 7;
        int w  = p & 127;
        int gh = hb + hh - 1;
        const bool ok = ((unsigned)s < (unsigned)T_) && ((unsigned)gh < (unsigned)H_);
        const float* xb = x + (size_t)bb*CIN*T_*HW + (size_t)s*HW + (size_t)gh*W_ + w;
        float f[CIN];
        #pragma unroll
        for (int ci = 0; ci < CIN; ci++)
            f[ci] = ok ? xb[(size_t)ci*T_*HW] : 0.f;
        #pragma unroll
        for (int j = 0; j < 8; j++) {
            __half2 h2 = __floats2half2_rn(f[2*j], f[2*j + 1]);
            v[pp*8 + j] = *(uint32_t*)&h2;
        }
    }
}

// Store slice into rolling slot: 4 STS.128, conflict-free.
__device__ __forceinline__ void store_slice(char* smem, int slot, int tid,
                                            const uint32_t v[16]) {
    #pragma unroll
    for (int pp = 0; pp < 2; pp++) {
        int p  = tid + pp*256;
        int hh = p >> 7;
        int w  = p & 127;
        int row = slot*520 + hh*130 + (w + 1);
        #pragma unroll
        for (int pl = 0; pl < 2; pl++) {
            uint4 q = make_uint4(v[pp*8 + pl*4], v[pp*8 + pl*4 + 1],
                                 v[pp*8 + pl*4 + 2], v[pp*8 + pl*4 + 3]);
            *(uint4*)(smem + SMEM_SLAB + pl*PLANE_B + row*16) = q;
        }
    }
}

__global__ __launch_bounds__(256, 2)
void qrnn_fused_kernel(const float* __restrict__ x,
                       const float* __restrict__ Wg,
                       const float* __restrict__ bias,
                       float* __restrict__ out)
{
#if TC_PATH
    extern __shared__ char smem[];
    const uint32_t smem_base = smem_u32(smem);
    float* s_bias = (float*)(smem + SMEM_BIAS);

    const int tid = threadIdx.x;
    const int wid = tid >> 5;
    const int hb  = blockIdx.x * 2;
    const int bb  = blockIdx.y;

    // ---- prologue ----
    if (wid == 0) {
        asm volatile("tcgen05.alloc.cta_group::1.sync.aligned.shared::cta.b32 [%0], %1;"
                     :: "r"(smem_base + SMEM_PTR), "r"(128u) : "memory");
        asm volatile("tcgen05.relinquish_alloc_permit.cta_group::1.sync.aligned;");
    }
    if (tid == 0) {
        asm volatile("mbarrier.init.shared.b64 [%0], %1;"
                     :: "r"(smem_base + SMEM_MBAR0), "r"(1u) : "memory");
        asm volatile("mbarrier.init.shared.b64 [%0], %1;"
                     :: "r"(smem_base + SMEM_MBAR1), "r"(1u) : "memory");
    }
    if (tid < 32) s_bias[tid] = bias[tid];

    // zero the A slab (covers halos, slice -1, and w-edge columns forever)
    for (int i = tid; i < (2*PLANE_B)/16; i += 256)
        *(uint4*)(smem + SMEM_SLAB + i*16) = make_uint4(0,0,0,0);

    // B: [co 32][k 432] K-major SW128 blocked atoms (HW-validated layout)
    for (int idx = tid; idx < 27*16*32; idx += 256) {
        int tap = idx % 27;
        int ci  = (idx / 27) & 15;
        int co  = idx / 432;
        int k   = tap*16 + ci;
        uint32_t byte_off = (uint32_t)(((co >> 3) + (k >> 6)*4)*1024
                                       + (co & 7)*128 + (k & 63)*2);
        *(__half*)(smem + SMEM_BMAT + SWZ128(byte_off)) = __float2half(Wg[idx]);
    }
    __syncthreads();   // slab zero visible before slice stores

    // preload slices 0,1,2 into slots 1,2,3 (slice -1 stays zero in slot 0)
    {
        uint32_t v0[16];
        load_slice(x, bb, hb, 0, tid, v0);
        store_slice(smem, 1, tid, v0);
        load_slice(x, bb, hb, 1, tid, v0);
        store_slice(smem, 2, tid, v0);
        load_slice(x, bb, hb, 2, tid, v0);
        store_slice(smem, 3, tid, v0);
    }
    asm volatile("fence.proxy.async.shared::cta;" ::: "memory");
    __syncthreads();

    uint32_t tmem_base;
    asm volatile("ld.shared.b32 %0, [%1];" : "=r"(tmem_base) : "r"(smem_base + SMEM_PTR));

    const uint64_t a_base = make_desc(smem_base + SMEM_SLAB, PLANE_B/16, 8, 0);
    const uint64_t b_base = make_desc(smem_base + SMEM_BMAT, 1, 64, 2);
    const bool issuer = (wid == 0) && elect_one();

    // epilogue mapping: warpgroup wg owns h-row hr = wg, px = w
    const int wg = tid >> 7;
    const int px = tid & 127;
    const size_t out_rowbase = (size_t)(hb + wg)*W_ + px;

    float hstate[HID];
    #pragma unroll
    for (int c = 0; c < HID; c++) hstate[c] = 0.f;
    float bz[HID], bf[HID];
    #pragma unroll
    for (int c = 0; c < HID; c++) { bz[c] = s_bias[c]; bf[c] = s_bias[c + HID]; }

    // ---- main loop: 2 timesteps per iteration ----
    for (int it = 0; it < (T_ + 1)/2; it++) {
        const int t = 2*it;

        // (1) issue both steps' MMAs (tiles 0,1 -> step t via mbar0;
        //     tiles 2,3 -> step t+1 via mbar1)
        if (issuer) {
            issue_step(t,     tmem_base,      a_base, b_base, smem_base + SMEM_MBAR0);
            issue_step(t + 1, tmem_base + 64, a_base, b_base, smem_base + SMEM_MBAR1);
        }

        // (2) prefetch slices t+3, t+4 (latency hidden by MMA execution)
        uint32_t v1[16], v2[16];
        load_slice(x, bb, hb, t + 3, tid, v1);
        load_slice(x, bb, hb, t + 4, tid, v2);

        // (3) step t: wait, free slot t&3 (slice t-1 dead) -> store slice t+3
        mbar_wait(smem_base + SMEM_MBAR0, it & 1);
        asm volatile("tcgen05.fence::after_thread_sync;" ::: "memory");
        store_slice(smem, t & 3, tid, v1);

        // (4) epilogue step t (overlaps step t+1 MMA execution)
        {
            uint32_t d[32];
            asm volatile(
                "tcgen05.ld.sync.aligned.32x32b.x32.b32 "
                "{%0,%1,%2,%3,%4,%5,%6,%7,%8,%9,%10,%11,%12,%13,%14,%15,"
                "%16,%17,%18,%19,%20,%21,%22,%23,%24,%25,%26,%27,%28,%29,%30,%31}, [%32];"
                : "=r"(d[0]),"=r"(d[1]),"=r"(d[2]),"=r"(d[3]),"=r"(d[4]),"=r"(d[5]),
                  "=r"(d[6]),"=r"(d[7]),"=r"(d[8]),"=r"(d[9]),"=r"(d[10]),"=r"(d[11]),
                  "=r"(d[12]),"=r"(d[13]),"=r"(d[14]),"=r"(d[15]),"=r"(d[16]),"=r"(d[17]),
                  "=r"(d[18]),"=r"(d[19]),"=r"(d[20]),"=r"(d[21]),"=r"(d[22]),"=r"(d[23]),
                  "=r"(d[24]),"=r"(d[25]),"=r"(d[26]),"=r"(d[27]),"=r"(d[28]),"=r"(d[29]),
                  "=r"(d[30]),"=r"(d[31])
                : "r"(tmem_base + wg*32));
            asm volatile("tcgen05.wait::ld.sync.aligned;" ::: "memory");
            #pragma unroll
            for (int c = 0; c < HID; c++) {
                float gz = __uint_as_float(d[c])       + bz[c];
                float gf = __uint_as_float(d[c + HID]) + bf[c];
                float z  = tanh_approx(gz);
                float f  = fmaf(tanh_approx(0.5f * gf), 0.5f, 0.5f);
                hstate[c] = f * (hstate[c] - z) + z;
                out[((size_t)(bb*HID + c)*T_ + t)*HW + out_rowbase] = hstate[c];
            }
        }

        // (5) step t+1: wait, free slot (t+1)&3 (slice t dead) -> store t+4
        mbar_wait(smem_base + SMEM_MBAR1, it & 1);
        asm volatile("tcgen05.fence::after_thread_sync;" ::: "memory");
        store_slice(smem, (t + 1) & 3, tid, v2);

        // (6) epilogue step t+1 (t+1 == 31 on last iter: MMA computed zeros,
        //     skip the read/update/store)
        if (t + 1 < T_) {
            uint32_t d[32];
            asm volatile(
                "tcgen05.ld.sync.aligned.32x32b.x32.b32 "
                "{%0,%1,%2,%3,%4,%5,%6,%7,%8,%9,%10,%11,%12,%13,%14,%15,"
                "%16,%17,%18,%19,%20,%21,%22,%23,%24,%25,%26,%27,%28,%29,%30,%31}, [%32];"
                : "=r"(d[0]),"=r"(d[1]),"=r"(d[2]),"=r"(d[3]),"=r"(d[4]),"=r"(d[5]),
                  "=r"(d[6]),"=r"(d[7]),"=r"(d[8]),"=r"(d[9]),"=r"(d[10]),"=r"(d[11]),
                  "=r"(d[12]),"=r"(d[13]),"=r"(d[14]),"=r"(d[15]),"=r"(d[16]),"=r"(d[17]),
                  "=r"(d[18]),"=r"(d[19]),"=r"(d[20]),"=r"(d[21]),"=r"(d[22]),"=r"(d[23]),
                  "=r"(d[24]),"=r"(d[25]),"=r"(d[26]),"=r"(d[27]),"=r"(d[28]),"=r"(d[29]),
                  "=r"(d[30]),"=r"(d[31])
                : "r"(tmem_base + 64 + wg*32));
            asm volatile("tcgen05.wait::ld.sync.aligned;" ::: "memory");
            #pragma unroll
            for (int c = 0; c < HID; c++) {
                float gz = __uint_as_float(d[c])       + bz[c];
                float gf = __uint_as_float(d[c + HID]) + bf[c];
                float z  = tanh_approx(gz);
                float f  = fmaf(tanh_approx(0.5f * gf), 0.5f, 0.5f);
                hstate[c] = f * (hstate[c] - z) + z;
                out[((size_t)(bb*HID + c)*T_ + (t + 1))*HW + out_rowbase] = hstate[c];
            }
        }

        // (7) one fence-pair + one sync per 2 steps: order slice stores
        //     (generic->async) and TMEM reads before next iter's MMAs.
        asm volatile("fence.proxy.async.shared::cta;" ::: "memory");
        asm volatile("tcgen05.fence::before_thread_sync;" ::: "memory");
        __syncthreads();
    }

    if (wid == 0)
        asm volatile("tcgen05.dealloc.cta_group::1.sync.aligned.b32 %0, %1;"
                     :: "r"(tmem_base), "r"(128u));
#endif  // TC_PATH
}

extern "C" void kernel_launch(void* const* d_in, const int* in_sizes, int n_in,
                              void* d_out, int out_size)
{
    (void)in_sizes; (void)n_in; (void)out_size;
    const float* x    = (const float*)d_in[0];
    const float* Wg   = (const float*)d_in[1];
    const float* bias = (const float*)d_in[2];
    float* out = (float*)d_out;

    cudaFuncSetAttribute(qrnn_fused_kernel,
                         cudaFuncAttributeMaxDynamicSharedMemorySize, SMEM_BYTES);

    dim3 grid(H_ / 2, B_);   // 64 x 4 = 256 CTAs, 2/SM resident -> 1 wave
    qrnn_fused_kernel<<<grid, 256, SMEM_BYTES>>>(x, Wg, bias, out);
}

// round 17
// speedup vs baseline: 1.3097x; 1.0358x over previous
#include <cuda_runtime.h>
#include <cuda_fp16.h>
#include <math.h>
#include <stdint.h>

// Problem constants
#define B_    4
#define CIN   16
#define T_    31
#define H_    128
#define W_    128
#define HID   16
#define HW    (H_*W_)

// Arch-specific feature gate: tcgen05 PTX only assembles for sm_103a/f targets.
#if (defined(__CUDA_ARCH_SPECIFIC__) && (__CUDA_ARCH_SPECIFIC__ >= 1000)) || \
    (defined(__CUDA_ARCH_FAMILY_SPECIFIC__) && (__CUDA_ARCH_FAMILY_SPECIFIC__ >= 1000))
#define TC_PATH 1
#else
#define TC_PATH 0
#endif

// ===========================================================================
// Persistent fused conv + fo-pool, 2 timesteps/iteration (R16 skeleton,
// 111.1us). R17: kernel is LSU-issue-bound on input loads (~2048 warp-LDG.32
// per SM-iter = ~3.7k cyc). Paired-pixel loading: thread owns ADJACENT
// pixels (2*tid, 2*tid+1) -> 16 LDG.64 per slice (was 32 LDG.32), halving
// LDG issue count. Cost: STS lane stride 32B -> 2-way phase conflict
// (+~0.5k cyc) vs -1.9k LDG issue. Also: skip load issue for slices >= T,
// skip entire second half on the last iteration (t+1 == 31).
// Base: 2 CTAs/SM x 2 h-rows x 256 thr, 4-slot slab, A two dense ci-planes
// LBO=plane/16 SBO=8 (HW-validated), B SW128 blocked atoms (HW-validated),
// double-commit TMEM tiles 0-3, 2-MUFU epilogue (R14-validated math).
// ===========================================================================
#define NROWS      2080                       // 4 slots * 520 rows
#define PLANE_B    (NROWS*16)                 // 33280 B per ci-plane
#define SMEM_SLAB  0
#define SMEM_BMAT  (2*PLANE_B)                // 66560, 1024-aligned
#define BMAT_BYTES (28*1024)
#define SMEM_PTR   (SMEM_BMAT + BMAT_BYTES)   // 95232
#define SMEM_MBAR0 (SMEM_PTR + 8)
#define SMEM_MBAR1 (SMEM_PTR + 16)
#define SMEM_BIAS  (SMEM_PTR + 32)
#define SMEM_BYTES (SMEM_BIAS + 128)

#define MMA_IDESC  0x8080010u                 // f16 in, f32 acc, M=128, N=32
#define SWZ128(x) ((x) ^ (((x) >> 3) & 0x70))

__device__ __forceinline__ uint32_t smem_u32(const void* p) {
    uint32_t a;
    asm("{ .reg .u64 t; cvta.to.shared.u64 t, %1; cvt.u32.u64 %0, t; }" : "=r"(a) : "l"(p));
    return a;
}

#if TC_PATH
__device__ __forceinline__ uint32_t elect_one() {
    uint32_t p;
    asm volatile("{\n\t.reg .pred p;\n\telect.sync _|p, 0xFFFFFFFF;\n\t"
                 "selp.b32 %0, 1, 0, p;\n\t}" : "=r"(p));
    return p;
}
__device__ __forceinline__ uint64_t make_desc(uint32_t addr, uint32_t lbo,
                                              uint32_t sbo, uint32_t layout) {
    uint64_t d = 0;
    d |= (uint64_t)(addr >> 4) & 0x3FFF;
    d |= ((uint64_t)lbo & 0x3FFF) << 16;
    d |= ((uint64_t)sbo & 0x3FFF) << 32;
    d |= (uint64_t)1 << 46;
    d |= ((uint64_t)layout & 0x7) << 61;
    return d;
}
__device__ __forceinline__ void mma_f16_ss(uint32_t d_tmem, uint64_t a_desc,
                                           uint64_t b_desc, uint32_t idesc,
                                           uint32_t enable) {
    asm volatile(
        "{\n\t.reg .pred p;\n\tsetp.ne.u32 p, %5, 0;\n\t"
        "tcgen05.mma.cta_group::1.kind::f16 [%0], %1, %2, %3, {%4,%4,%4,%4}, p;\n\t}"
        :: "r"(d_tmem), "l"(a_desc), "l"(b_desc), "r"(idesc), "r"(0u), "r"(enable)
        : "memory");
}
__device__ __forceinline__ void mbar_wait(uint32_t m, uint32_t parity) {
    uint32_t done;
    asm volatile("{\n\t.reg .pred p;\n\t"
        "mbarrier.try_wait.parity.acquire.cta.shared::cta.b64 p, [%1], %2;\n\t"
        "selp.b32 %0, 1, 0, p;\n\t}" : "=r"(done) : "r"(m), "r"(parity) : "memory");
    while (!done)
        asm volatile("{\n\t.reg .pred p;\n\t"
            "mbarrier.try_wait.parity.acquire.cta.shared::cta.b64 p, [%1], %2, 0x989680;\n\t"
            "selp.b32 %0, 1, 0, p;\n\t}" : "=r"(done) : "r"(m), "r"(parity) : "memory");
}

// Issue the 54 MMAs for one time step into D buffer (tmem_d), commit to mbar.
__device__ __forceinline__ void issue_step(int t, uint32_t tmem_d,
                                           uint64_t a_base, uint64_t b_base,
                                           uint32_t mbar) {
    #pragma unroll
    for (int hr = 0; hr < 2; hr++) {
        #pragma unroll
        for (int kc = 0; kc < 27; kc++) {
            const int kd = kc / 9, kh = (kc / 3) % 3, kw = kc % 3;
            const int rowoff = ((t + kd) & 3)*520 + (hr + kh)*130 + kw;
            mma_f16_ss(tmem_d + hr*32,
                       a_base + (uint64_t)rowoff,
                       b_base + (uint64_t)((kc >> 2)*256 + (kc & 3)*2),
                       MMA_IDESC, kc > 0);
        }
    }
    asm volatile(
        "tcgen05.commit.cta_group::1.mbarrier::arrive::one.shared::cluster.b64 [%0];"
        :: "r"(mbar) : "memory");
}
__device__ __forceinline__ float tanh_approx(float x) {
    float r;
    asm("tanh.approx.f32 %0, %1;" : "=f"(r) : "f"(x));
    return r;
}
#endif

// Load one t-slice: thread owns ADJACENT pixels 2*tid, 2*tid+1
// (hh = tid>>6, w = (tid&63)*2). Per ci-pair: two float2 loads cover both
// pixels -> 16 LDG.64 total. Uniform skip when slice out of range.
// v[0..7] = even pixel (ci pairs 0..7), v[8..15] = odd pixel.
__device__ __forceinline__ void load_slice(const float* __restrict__ x,
                                           int bb, int hb, int s, int tid,
                                           uint32_t v[16]) {
    if ((unsigned)s >= (unsigned)T_) {
        #pragma unroll
        for (int j = 0; j < 16; j++) v[j] = 0;
        return;
    }
    const int hh = tid >> 6;
    const int w  = (tid & 63) * 2;
    const int gh = hb + hh - 1;
    const bool ok = (unsigned)gh < (unsigned)H_;
    const float* xb = x + ((size_t)(bb*CIN)*T_ + s)*HW + (size_t)gh*W_ + w;
    #pragma unroll
    for (int j = 0; j < 8; j++) {
        float2 a0 = make_float2(0.f, 0.f), a1 = make_float2(0.f, 0.f);
        if (ok) {
            a0 = *(const float2*)(xb + (size_t)(2*j    )*T_*HW);
            a1 = *(const float2*)(xb + (size_t)(2*j + 1)*T_*HW);
        }
        __half2 p0 = __floats2half2_rn(a0.x, a1.x);   // even px, ci {2j,2j+1}
        __half2 p1 = __floats2half2_rn(a0.y, a1.y);   // odd  px
        v[j]     = *(uint32_t*)&p0;
        v[8 + j] = *(uint32_t*)&p1;
    }
}

// Store slice into rolling slot: rows 2*tid, 2*tid+1 (+1 w-halo shift),
// 4 STS.128 per thread (2 planes x 2 pixels). 2-way phase conflict (32B
// lane stride) — accepted tradeoff for halved LDG issue.
__device__ __forceinline__ void store_slice(char* smem, int slot, int tid,
                                            const uint32_t v[16]) {
    const int hh  = tid >> 6;
    const int w   = (tid & 63) * 2;
    const int row = slot*520 + hh*130 + (w + 1);   // even px row; odd = row+1
    #pragma unroll
    for (int pl = 0; pl < 2; pl++) {
        uint4 qe = make_uint4(v[pl*4], v[pl*4 + 1], v[pl*4 + 2], v[pl*4 + 3]);
        uint4 qo = make_uint4(v[8 + pl*4], v[8 + pl*4 + 1],
                              v[8 + pl*4 + 2], v[8 + pl*4 + 3]);
        *(uint4*)(smem + SMEM_SLAB + pl*PLANE_B + row*16)       = qe;
        *(uint4*)(smem + SMEM_SLAB + pl*PLANE_B + (row + 1)*16) = qo;
    }
}

__global__ __launch_bounds__(256, 2)
void qrnn_fused_kernel(const float* __restrict__ x,
                       const float* __restrict__ Wg,
                       const float* __restrict__ bias,
                       float* __restrict__ out)
{
#if TC_PATH
    extern __shared__ char smem[];
    const uint32_t smem_base = smem_u32(smem);
    float* s_bias = (float*)(smem + SMEM_BIAS);

    const int tid = threadIdx.x;
    const int wid = tid >> 5;
    const int hb  = blockIdx.x * 2;
    const int bb  = blockIdx.y;

    // ---- prologue ----
    if (wid == 0) {
        asm volatile("tcgen05.alloc.cta_group::1.sync.aligned.shared::cta.b32 [%0], %1;"
                     :: "r"(smem_base + SMEM_PTR), "r"(128u) : "memory");
        asm volatile("tcgen05.relinquish_alloc_permit.cta_group::1.sync.aligned;");
    }
    if (tid == 0) {
        asm volatile("mbarrier.init.shared.b64 [%0], %1;"
                     :: "r"(smem_base + SMEM_MBAR0), "r"(1u) : "memory");
        asm volatile("mbarrier.init.shared.b64 [%0], %1;"
                     :: "r"(smem_base + SMEM_MBAR1), "r"(1u) : "memory");
    }
    if (tid < 32) s_bias[tid] = bias[tid];

    // zero the A slab (covers halos, slice -1, and w-edge columns forever)
    for (int i = tid; i < (2*PLANE_B)/16; i += 256)
        *(uint4*)(smem + SMEM_SLAB + i*16) = make_uint4(0,0,0,0);

    // B: [co 32][k 432] K-major SW128 blocked atoms (HW-validated layout)
    for (int idx = tid; idx < 27*16*32; idx += 256) {
        int tap = idx % 27;
        int ci  = (idx / 27) & 15;
        int co  = idx / 432;
        int k   = tap*16 + ci;
        uint32_t byte_off = (uint32_t)(((co >> 3) + (k >> 6)*4)*1024
                                       + (co & 7)*128 + (k & 63)*2);
        *(__half*)(smem + SMEM_BMAT + SWZ128(byte_off)) = __float2half(Wg[idx]);
    }
    __syncthreads();   // slab zero visible before slice stores

    // preload slices 0,1,2 into slots 1,2,3 (slice -1 stays zero in slot 0)
    {
        uint32_t v0[16];
        load_slice(x, bb, hb, 0, tid, v0);
        store_slice(smem, 1, tid, v0);
        load_slice(x, bb, hb, 1, tid, v0);
        store_slice(smem, 2, tid, v0);
        load_slice(x, bb, hb, 2, tid, v0);
        store_slice(smem, 3, tid, v0);
    }
    asm volatile("fence.proxy.async.shared::cta;" ::: "memory");
    __syncthreads();

    uint32_t tmem_base;
    asm volatile("ld.shared.b32 %0, [%1];" : "=r"(tmem_base) : "r"(smem_base + SMEM_PTR));

    const uint64_t a_base = make_desc(smem_base + SMEM_SLAB, PLANE_B/16, 8, 0);
    const uint64_t b_base = make_desc(smem_base + SMEM_BMAT, 1, 64, 2);
    const bool issuer = (wid == 0) && elect_one();

    // epilogue mapping: warpgroup wg owns h-row hr = wg, px = w
    const int wg = tid >> 7;
    const int px = tid & 127;
    const size_t out_rowbase = (size_t)(hb + wg)*W_ + px;

    float hstate[HID];
    #pragma unroll
    for (int c = 0; c < HID; c++) hstate[c] = 0.f;
    float bz[HID], bf[HID];
    #pragma unroll
    for (int c = 0; c < HID; c++) { bz[c] = s_bias[c]; bf[c] = s_bias[c + HID]; }

    // ---- main loop: 2 timesteps per iteration ----
    for (int it = 0; it < (T_ + 1)/2; it++) {
        const int t = 2*it;
        const bool has2 = (t + 1 < T_);   // last iter (t=30): single step

        // (1) issue MMAs (tiles 0,1 -> step t / mbar0; tiles 2,3 -> t+1 / mbar1)
        if (issuer) {
            issue_step(t, tmem_base, a_base, b_base, smem_base + SMEM_MBAR0);
            if (has2)
                issue_step(t + 1, tmem_base + 64, a_base, b_base,
                           smem_base + SMEM_MBAR1);
        }

        // (2) prefetch slices t+3, t+4 (out-of-range -> zero regs, no LDG)
        uint32_t v1[16], v2[16];
        load_slice(x, bb, hb, t + 3, tid, v1);
        if (has2) load_slice(x, bb, hb, t + 4, tid, v2);

        // (3) step t: wait, free slot t&3 (slice t-1 dead) -> store slice t+3
        mbar_wait(smem_base + SMEM_MBAR0, it & 1);
        asm volatile("tcgen05.fence::after_thread_sync;" ::: "memory");
        store_slice(smem, t & 3, tid, v1);

        // (4) epilogue step t (overlaps step t+1 MMA execution)
        {
            uint32_t d[32];
            asm volatile(
                "tcgen05.ld.sync.aligned.32x32b.x32.b32 "
                "{%0,%1,%2,%3,%4,%5,%6,%7,%8,%9,%10,%11,%12,%13,%14,%15,"
                "%16,%17,%18,%19,%20,%21,%22,%23,%24,%25,%26,%27,%28,%29,%30,%31}, [%32];"
                : "=r"(d[0]),"=r"(d[1]),"=r"(d[2]),"=r"(d[3]),"=r"(d[4]),"=r"(d[5]),
                  "=r"(d[6]),"=r"(d[7]),"=r"(d[8]),"=r"(d[9]),"=r"(d[10]),"=r"(d[11]),
                  "=r"(d[12]),"=r"(d[13]),"=r"(d[14]),"=r"(d[15]),"=r"(d[16]),"=r"(d[17]),
                  "=r"(d[18]),"=r"(d[19]),"=r"(d[20]),"=r"(d[21]),"=r"(d[22]),"=r"(d[23]),
                  "=r"(d[24]),"=r"(d[25]),"=r"(d[26]),"=r"(d[27]),"=r"(d[28]),"=r"(d[29]),
                  "=r"(d[30]),"=r"(d[31])
                : "r"(tmem_base + wg*32));
            asm volatile("tcgen05.wait::ld.sync.aligned;" ::: "memory");
            #pragma unroll
            for (int c = 0; c < HID; c++) {
                float gz = __uint_as_float(d[c])       + bz[c];
                float gf = __uint_as_float(d[c + HID]) + bf[c];
                float z  = tanh_approx(gz);
                float f  = fmaf(tanh_approx(0.5f * gf), 0.5f, 0.5f);
                hstate[c] = f * (hstate[c] - z) + z;
                out[((size_t)(bb*HID + c)*T_ + t)*HW + out_rowbase] = hstate[c];
            }
        }

        if (has2) {
            // (5) step t+1: wait, free slot (t+1)&3 (slice t dead) -> store t+4
            mbar_wait(smem_base + SMEM_MBAR1, it & 1);
            asm volatile("tcgen05.fence::after_thread_sync;" ::: "memory");
            store_slice(smem, (t + 1) & 3, tid, v2);

            // (6) epilogue step t+1
            uint32_t d[32];
            asm volatile(
                "tcgen05.ld.sync.aligned.32x32b.x32.b32 "
                "{%0,%1,%2,%3,%4,%5,%6,%7,%8,%9,%10,%11,%12,%13,%14,%15,"
                "%16,%17,%18,%19,%20,%21,%22,%23,%24,%25,%26,%27,%28,%29,%30,%31}, [%32];"
                : "=r"(d[0]),"=r"(d[1]),"=r"(d[2]),"=r"(d[3]),"=r"(d[4]),"=r"(d[5]),
                  "=r"(d[6]),"=r"(d[7]),"=r"(d[8]),"=r"(d[9]),"=r"(d[10]),"=r"(d[11]),
                  "=r"(d[12]),"=r"(d[13]),"=r"(d[14]),"=r"(d[15]),"=r"(d[16]),"=r"(d[17]),
                  "=r"(d[18]),"=r"(d[19]),"=r"(d[20]),"=r"(d[21]),"=r"(d[22]),"=r"(d[23]),
                  "=r"(d[24]),"=r"(d[25]),"=r"(d[26]),"=r"(d[27]),"=r"(d[28]),"=r"(d[29]),
                  "=r"(d[30]),"=r"(d[31])
                : "r"(tmem_base + 64 + wg*32));
            asm volatile("tcgen05.wait::ld.sync.aligned;" ::: "memory");
            #pragma unroll
            for (int c = 0; c < HID; c++) {
                float gz = __uint_as_float(d[c])       + bz[c];
                float gf = __uint_as_float(d[c + HID]) + bf[c];
                float z  = tanh_approx(gz);
                float f  = fmaf(tanh_approx(0.5f * gf), 0.5f, 0.5f);
                hstate[c] = f * (hstate[c] - z) + z;
                out[((size_t)(bb*HID + c)*T_ + (t + 1))*HW + out_rowbase] = hstate[c];
            }
        }

        // (7) one fence-pair + one sync per iteration.
        asm volatile("fence.proxy.async.shared::cta;" ::: "memory");
        asm volatile("tcgen05.fence::before_thread_sync;" ::: "memory");
        __syncthreads();
    }

    if (wid == 0)
        asm volatile("tcgen05.dealloc.cta_group::1.sync.aligned.b32 %0, %1;"
                     :: "r"(tmem_base), "r"(128u));
#endif  // TC_PATH
}

extern "C" void kernel_launch(void* const* d_in, const int* in_sizes, int n_in,
                              void* d_out, int out_size)
{
    (void)in_sizes; (void)n_in; (void)out_size;
    const float* x    = (const float*)d_in[0];
    const float* Wg   = (const float*)d_in[1];
    const float* bias = (const float*)d_in[2];
    float* out = (float*)d_out;

    cudaFuncSetAttribute(qrnn_fused_kernel,
                         cudaFuncAttributeMaxDynamicSharedMemorySize, SMEM_BYTES);

    dim3 grid(H_ / 2, B_);   // 64 x 4 = 256 CTAs, 2/SM resident -> 1 wave
    qrnn_fused_kernel<<<grid, 256, SMEM_BYTES>>>(x, Wg, bias, out);
}